// round 7
// baseline (speedup 1.0000x reference)
#include <cuda_runtime.h>
#include <math.h>

// features: (1, 50, 50, 1024) fp32 NHWC ; boxes: (1, 300, 4) fp32 [y1,x1,y2,x2]
// crop 14x14 bilinear, 2x2 max pool -> out (1, 300, 7, 7, 1024) fp32
// Block = one (box, py) pooled row: rows shared across all 7 px outputs.
// 64 threads/block, each thread does 4 channel groups (c4 + k*64).

#define FH 50
#define FW 50
#define FC 1024
#define NBOX 300
#define CROP 14
#define PO 7
#define C4 (FC / 4)      // 256 float4 channel groups
#define TPB 64
#define CG  4            // channel groups per thread
#define ROWS4 (FW * C4)

__device__ __forceinline__ float4 wsum(const float4 tl, const float4 tr,
                                       const float4 bl, const float4 br,
                                       const float a, const float b)
{
    const float aa = 1.0f - a;
    const float bb = 1.0f - b;
    const float w0 = aa * bb, w1 = a * bb, w2 = aa * b, w3 = a * b;
    float4 v;
    v.x = fmaf(w3, br.x, fmaf(w2, bl.x, fmaf(w1, tr.x, w0 * tl.x)));
    v.y = fmaf(w3, br.y, fmaf(w2, bl.y, fmaf(w1, tr.y, w0 * tl.y)));
    v.z = fmaf(w3, br.z, fmaf(w2, bl.z, fmaf(w1, tr.z, w0 * tl.z)));
    v.w = fmaf(w3, br.w, fmaf(w2, bl.w, fmaf(w1, tr.w, w0 * tl.w)));
    return v;
}

__device__ __forceinline__ void max4(float4& m, const float4 v)
{
    m.x = fmaxf(m.x, v.x);
    m.y = fmaxf(m.y, v.y);
    m.z = fmaxf(m.z, v.z);
    m.w = fmaxf(m.w, v.w);
}

// One pooled output pixel, all CG channel groups of this thread.
// YC/XC: 0 = same pair, 1 = chain (3 contiguous), 2 = disjoint pairs.
template <int YC, int XC>
__device__ __forceinline__ void do_px(
    const float4* __restrict__ p,    // f4 + (r0*FW + c0)*C4 + c4
    float4* __restrict__ optr,       // out + (outpix)*C4 + c4
    const int dr, const int dc,
    const float wy0, const float wy1, const float wx0, const float wx1)
{
    constexpr int NC = XC + 2;
    constexpr int XL1 = (XC == 0) ? 0 : ((XC == 1) ? 1 : 2);

    int coff[NC];
    coff[0] = 0;
    coff[1] = C4;
    if (XC == 1) { coff[2] = 2 * C4; }
    if (XC == 2) { coff[2] = dc * C4; coff[3] = coff[2] + C4; }

#pragma unroll 1
    for (int cg = 0; cg < CG; cg++) {
        const int off = cg * TPB;

        // ---- top band: rows 0,1 ----
        float4 a0[NC], a1[NC];
#pragma unroll
        for (int j = 0; j < NC; j++) a0[j] = p[coff[j] + off];
#pragma unroll
        for (int j = 0; j < NC; j++) a1[j] = p[ROWS4 + coff[j] + off];

        float4 m = wsum(a0[0], a0[1], a1[0], a1[1], wx0, wy0);
        max4(m, wsum(a0[XL1], a0[XL1 + 1], a1[XL1], a1[XL1 + 1], wx1, wy0));

        // ---- bottom band ----
        if (YC == 1) {
#pragma unroll
            for (int j = 0; j < NC; j++) a0[j] = p[2 * ROWS4 + coff[j] + off];
            max4(m, wsum(a1[0], a1[1], a0[0], a0[1], wx0, wy1));
            max4(m, wsum(a1[XL1], a1[XL1 + 1], a0[XL1], a0[XL1 + 1], wx1, wy1));
        } else if (YC == 2) {
#pragma unroll
            for (int j = 0; j < NC; j++) a0[j] = p[dr * ROWS4 + coff[j] + off];
#pragma unroll
            for (int j = 0; j < NC; j++) a1[j] = p[(dr + 1) * ROWS4 + coff[j] + off];
            max4(m, wsum(a0[0], a0[1], a1[0], a1[1], wx0, wy1));
            max4(m, wsum(a0[XL1], a0[XL1 + 1], a1[XL1], a1[XL1 + 1], wx1, wy1));
        } else {
            max4(m, wsum(a0[0], a0[1], a1[0], a1[1], wx0, wy1));
            max4(m, wsum(a0[XL1], a0[XL1 + 1], a1[XL1], a1[XL1 + 1], wx1, wy1));
        }

        optr[off] = m;
    }
}

// Loop over the 7 px of this pooled row; rows (and wy) fixed.
template <int YC>
__device__ __forceinline__ void do_row(
    const float4* __restrict__ prow,  // f4 + r0*ROWS4 + c4
    float4* __restrict__ orow,        // out + (box*49 + py*7)*C4 + c4
    const int dr,
    const float xbase, const float dx,
    const float wy0, const float wy1)
{
    for (int px = 0; px < PO; px++) {
        const float xs0 = xbase + (float)(2 * px) * dx;
        const float xs1 = xs0 + dx;
        const float xf0 = floorf(xs0), xf1 = floorf(xs1);
        const float wx0 = xs0 - xf0, wx1 = xs1 - xf1;

        const int c0 = min(max((int)xf0, 0), FW - 2);
        const int c2 = min(max((int)xf1, 0), FW - 2);
        const int dc = c2 - c0;

        const float4* p = prow + c0 * C4;
        float4* o = orow + px * C4;

        if (dc == 0)      do_px<YC, 0>(p, o, dr, dc, wy0, wy1, wx0, wx1);
        else if (dc == 1) do_px<YC, 1>(p, o, dr, dc, wy0, wy1, wx0, wx1);
        else              do_px<YC, 2>(p, o, dr, dc, wy0, wy1, wx0, wx1);
    }
}

__global__ __launch_bounds__(TPB, 16)
void roi_pool_kernel(const float* __restrict__ feat,
                     const float* __restrict__ boxes,
                     float* __restrict__ out)
{
    const int bid = blockIdx.x;          // 0 .. 2100
    const int n   = bid / PO;            // box
    const int py  = bid - n * PO;        // pooled row
    const int c4  = threadIdx.x;         // base channel group

    const float4 box = ((const float4*)boxes)[n];
    const float by1 = box.x, bx1 = box.y, by2 = box.z, bx2 = box.w;

    const float scale = 1.0f / (float)(CROP - 1);
    const float dy = (by2 - by1) * (float)(FH - 1) * scale;
    const float dx = (bx2 - bx1) * (float)(FW - 1) * scale;
    const float ybase = by1 * (float)(FH - 1);
    const float xbase = bx1 * (float)(FW - 1);

    const float ys0 = ybase + (float)(2 * py) * dy;
    const float ys1 = ys0 + dy;
    const float yf0 = floorf(ys0), yf1 = floorf(ys1);
    const float wy0 = ys0 - yf0, wy1 = ys1 - yf1;

    // Clamps never fire on in-range data (coords in [0,49)).
    const int r0 = min(max((int)yf0, 0), FH - 2);
    const int r2 = min(max((int)yf1, 0), FH - 2);
    const int dr = r2 - r0;

    const float4* __restrict__ prow = (const float4*)feat + (r0 * ROWS4 + c4);
    float4* __restrict__ orow = (float4*)out + (bid * PO * C4 + c4);

    if (dr == 0)      do_row<0>(prow, orow, dr, xbase, dx, wy0, wy1);
    else if (dr == 1) do_row<1>(prow, orow, dr, xbase, dx, wy0, wy1);
    else              do_row<2>(prow, orow, dr, xbase, dx, wy0, wy1);
}

extern "C" void kernel_launch(void* const* d_in, const int* in_sizes, int n_in,
                              void* d_out, int out_size)
{
    const float* feat  = (const float*)d_in[0];
    const float* boxes = (const float*)d_in[1];
    float* out = (float*)d_out;

    roi_pool_kernel<<<NBOX * PO, TPB>>>(feat, boxes, out);
}

// round 8
// speedup vs baseline: 1.0009x; 1.0009x over previous
#include <cuda_runtime.h>
#include <math.h>

// features: (1, 50, 50, 1024) fp32 NHWC ; boxes: (1, 300, 4) fp32 [y1,x1,y2,x2]
// crop 14x14 bilinear, 2x2 max pool -> out (1, 300, 7, 7, 1024) fp32
// Block = (box, pooled-row, channel-half). 128 threads, 1 float4 group each.
// The 7 px of a pooled row share rows + ~half their columns; with ~20KB
// working set per block, reuse survives in L1 across the px loop.

#define FH 50
#define FW 50
#define FC 1024
#define NBOX 300
#define CROP 14
#define PO 7
#define C4 (FC / 4)      // 256 float4 channel groups
#define TPB 128
#define ROWS4 (FW * C4)

__device__ __forceinline__ float4 wsum(const float4 tl, const float4 tr,
                                       const float4 bl, const float4 br,
                                       const float a, const float b)
{
    const float aa = 1.0f - a;
    const float bb = 1.0f - b;
    const float w0 = aa * bb, w1 = a * bb, w2 = aa * b, w3 = a * b;
    float4 v;
    v.x = fmaf(w3, br.x, fmaf(w2, bl.x, fmaf(w1, tr.x, w0 * tl.x)));
    v.y = fmaf(w3, br.y, fmaf(w2, bl.y, fmaf(w1, tr.y, w0 * tl.y)));
    v.z = fmaf(w3, br.z, fmaf(w2, bl.z, fmaf(w1, tr.z, w0 * tl.z)));
    v.w = fmaf(w3, br.w, fmaf(w2, bl.w, fmaf(w1, tr.w, w0 * tl.w)));
    return v;
}

__device__ __forceinline__ void max4(float4& m, const float4 v)
{
    m.x = fmaxf(m.x, v.x);
    m.y = fmaxf(m.y, v.y);
    m.z = fmaxf(m.z, v.z);
    m.w = fmaxf(m.w, v.w);
}

// One output px (single channel group). YC/XC: 0 = same pair, 1 = chain
// (3 contiguous), 2 = disjoint pairs (distance dr/dc).
template <int YC, int XC>
__device__ __forceinline__ void do_px(
    const float4* __restrict__ p,    // f4 + (r0*FW + c0)*C4 + c4
    float4* __restrict__ optr,
    const int dr, const int dc,
    const float wy0, const float wy1, const float wx0, const float wx1)
{
    constexpr int NC = XC + 2;
    constexpr int XL1 = (XC == 0) ? 0 : ((XC == 1) ? 1 : 2);

    int coff[NC];
    coff[0] = 0;
    coff[1] = C4;
    if (XC == 1) { coff[2] = 2 * C4; }
    if (XC == 2) { coff[2] = dc * C4; coff[3] = coff[2] + C4; }

    // ---- top band: rows 0,1 ----
    float4 a0[NC], a1[NC];
#pragma unroll
    for (int j = 0; j < NC; j++) a0[j] = p[coff[j]];
#pragma unroll
    for (int j = 0; j < NC; j++) a1[j] = p[ROWS4 + coff[j]];

    float4 m = wsum(a0[0], a0[1], a1[0], a1[1], wx0, wy0);
    max4(m, wsum(a0[XL1], a0[XL1 + 1], a1[XL1], a1[XL1 + 1], wx1, wy0));

    // ---- bottom band ----
    if (YC == 1) {
#pragma unroll
        for (int j = 0; j < NC; j++) a0[j] = p[2 * ROWS4 + coff[j]];
        max4(m, wsum(a1[0], a1[1], a0[0], a0[1], wx0, wy1));
        max4(m, wsum(a1[XL1], a1[XL1 + 1], a0[XL1], a0[XL1 + 1], wx1, wy1));
    } else if (YC == 2) {
#pragma unroll
        for (int j = 0; j < NC; j++) a0[j] = p[dr * ROWS4 + coff[j]];
#pragma unroll
        for (int j = 0; j < NC; j++) a1[j] = p[(dr + 1) * ROWS4 + coff[j]];
        max4(m, wsum(a0[0], a0[1], a1[0], a1[1], wx0, wy1));
        max4(m, wsum(a0[XL1], a0[XL1 + 1], a1[XL1], a1[XL1 + 1], wx1, wy1));
    } else {
        max4(m, wsum(a0[0], a0[1], a1[0], a1[1], wx0, wy1));
        max4(m, wsum(a0[XL1], a0[XL1 + 1], a1[XL1], a1[XL1 + 1], wx1, wy1));
    }

    *optr = m;
}

// Loop over the 7 px of this pooled row; rows (and wy, YC) fixed.
template <int YC>
__device__ __forceinline__ void do_row(
    const float4* __restrict__ prow,  // f4 + r0*ROWS4 + c4
    float4* __restrict__ orow,        // out + (box*49 + py*7)*C4 + c4
    const int dr,
    const float xbase, const float dx,
    const float wy0, const float wy1)
{
#pragma unroll
    for (int px = 0; px < PO; px++) {
        const float xs0 = xbase + (float)(2 * px) * dx;
        const float xs1 = xs0 + dx;
        const float xf0 = floorf(xs0), xf1 = floorf(xs1);
        const float wx0 = xs0 - xf0, wx1 = xs1 - xf1;

        const int c0 = min(max((int)xf0, 0), FW - 2);
        const int c2 = min(max((int)xf1, 0), FW - 2);
        const int dc = c2 - c0;

        const float4* p = prow + c0 * C4;
        float4* o = orow + px * C4;

        if (dc == 0)      do_px<YC, 0>(p, o, dr, dc, wy0, wy1, wx0, wx1);
        else if (dc == 1) do_px<YC, 1>(p, o, dr, dc, wy0, wy1, wx0, wx1);
        else              do_px<YC, 2>(p, o, dr, dc, wy0, wy1, wx0, wx1);
    }
}

__global__ __launch_bounds__(TPB, 8)
void roi_pool_kernel(const float* __restrict__ feat,
                     const float* __restrict__ boxes,
                     float* __restrict__ out)
{
    const int bid  = blockIdx.x;           // 0 .. 4200
    const int n    = bid / (PO * 2);       // box
    const int rem  = bid - n * (PO * 2);
    const int py   = rem >> 1;             // pooled row
    const int half = rem & 1;              // channel half
    const int c4   = half * TPB + threadIdx.x;

    const float4 box = ((const float4*)boxes)[n];
    const float by1 = box.x, bx1 = box.y, by2 = box.z, bx2 = box.w;

    const float scale = 1.0f / (float)(CROP - 1);
    const float dy = (by2 - by1) * (float)(FH - 1) * scale;
    const float dx = (bx2 - bx1) * (float)(FW - 1) * scale;
    const float ybase = by1 * (float)(FH - 1);
    const float xbase = bx1 * (float)(FW - 1);

    const float ys0 = ybase + (float)(2 * py) * dy;
    const float ys1 = ys0 + dy;
    const float yf0 = floorf(ys0), yf1 = floorf(ys1);
    const float wy0 = ys0 - yf0, wy1 = ys1 - yf1;

    // Clamps never fire on in-range data (coords in [0,49)).
    const int r0 = min(max((int)yf0, 0), FH - 2);
    const int r2 = min(max((int)yf1, 0), FH - 2);
    const int dr = r2 - r0;

    const float4* __restrict__ prow = (const float4*)feat + (r0 * ROWS4 + c4);
    float4* __restrict__ orow =
        (float4*)out + ((n * PO + py) * PO * C4 + c4);

    if (dr == 0)      do_row<0>(prow, orow, dr, xbase, dx, wy0, wy1);
    else if (dr == 1) do_row<1>(prow, orow, dr, xbase, dx, wy0, wy1);
    else              do_row<2>(prow, orow, dr, xbase, dx, wy0, wy1);
}

extern "C" void kernel_launch(void* const* d_in, const int* in_sizes, int n_in,
                              void* d_out, int out_size)
{
    const float* feat  = (const float*)d_in[0];
    const float* boxes = (const float*)d_in[1];
    float* out = (float*)d_out;

    roi_pool_kernel<<<NBOX * PO * 2, TPB>>>(feat, boxes, out);
}